// round 15
// baseline (speedup 1.0000x reference)
#include <cuda_runtime.h>
#include <cuda_fp16.h>
#include <cstdint>

#define NN 100000
#define NE 1600000
#define C  128
#define CAP 64                          // fixed CSR bucket capacity per node

// ---------------- device scratch (no allocations allowed) ----------------
__device__ int      g_cursor[NN];
__device__ int      g_csr[(size_t)NN * CAP];   // 25.6 MB bucket CSR
__device__ uint32_t g_x16[(size_t)NN * 64];    // x     as half2 words [NN][64]
__device__ uint32_t g_mean16[(size_t)NN * 64]; // mean  as half2 words
__device__ uint32_t g_h16[(size_t)NN * 64];    // h     as half2 words
__device__ uint32_t g_W1l_h[C * C / 2];        // weights as half2 words [C][64]
__device__ uint32_t g_W1r_h[C * C / 2];
__device__ uint32_t g_W2l_h[C * C / 2];
__device__ uint32_t g_W2r_h[C * C / 2];

__device__ __forceinline__ uint32_t pack_h2(float a, float b) {
    __half2 h = __floats2half2_rn(a, b);
    return *(uint32_t*)&h;
}

// Per-block edge dtype detection (first 64 high words; L2-hot).
__device__ __forceinline__ int detect_is64_block(const void* ei) {
    __shared__ int s_is64;
    if (threadIdx.x < 32) {
        const int* w = (const int*)ei;
        int nz = (w[2 * threadIdx.x + 1] != 0) ? 1 : 0;
        unsigned m = __ballot_sync(0xffffffff, nz);
        if (threadIdx.x == 0) s_is64 = (m == 0);
    }
    __syncthreads();
    return s_is64;
}

__device__ __forceinline__ int4 edge4_at(const void* ei, int base, int is64) {
    if (is64) {
        const longlong2* p = (const longlong2*)((const long long*)ei + base);
        longlong2 u = p[0];
        longlong2 v = p[1];
        return make_int4((int)u.x, (int)u.y, (int)v.x, (int)v.y);
    }
    return *(const int4*)((const int*)ei + base);
}

// ---------------- launch 0: cvt x/W -> fp16, cursor init ----------------
__global__ void __launch_bounds__(256) init_cvt_k(const float4* __restrict__ x4,
                                                  const float* __restrict__ W1l,
                                                  const float* __restrict__ W1r,
                                                  const float* __restrict__ W2l,
                                                  const float* __restrict__ W2r) {
    int i = blockIdx.x * 256 + threadIdx.x;
    if (i < NN * 32) {
        float4 v = x4[i];
        ((uint2*)g_x16)[i] = make_uint2(pack_h2(v.x, v.y), pack_h2(v.z, v.w));
    }
    if (i < NN) g_cursor[i] = i * CAP;
    if (i < C * C / 2) {
        g_W1l_h[i] = pack_h2(W1l[2 * i], W1l[2 * i + 1]);
        g_W1r_h[i] = pack_h2(W1r[2 * i], W1r[2 * i + 1]);
        g_W2l_h[i] = pack_h2(W2l[2 * i], W2l[2 * i + 1]);
        g_W2r_h[i] = pack_h2(W2r[2 * i], W2r[2 * i + 1]);
    }
}

// ---------------- launch 1: bucket CSR fill, 4 edges/thread ----------------
__global__ void __launch_bounds__(256) csr_fill_k(const void* __restrict__ ei) {
    int is64 = detect_is64_block(ei);
    int t = blockIdx.x * 256 + threadIdx.x;
    if (t < NE / 4) {
        int4 s = edge4_at(ei, t * 4, is64);
        int4 d = edge4_at(ei, NE + t * 4, is64);
        g_csr[atomicAdd(&g_cursor[d.x], 1)] = s.x;
        g_csr[atomicAdd(&g_cursor[d.y], 1)] = s.y;
        g_csr[atomicAdd(&g_cursor[d.z], 1)] = s.z;
        g_csr[atomicAdd(&g_cursor[d.w], 1)] = s.w;
    }
}

// ---------------- aggregate: fp16 mean, half-warp rows, bucket offsets ------
__device__ __forceinline__ void acc_pair4(float4& a, float4& b, uint4 u, uint4 v) {
    __half2 s0 = __hadd2(*(__half2*)&u.x, *(__half2*)&v.x);
    __half2 s1 = __hadd2(*(__half2*)&u.y, *(__half2*)&v.y);
    __half2 s2 = __hadd2(*(__half2*)&u.z, *(__half2*)&v.z);
    __half2 s3 = __hadd2(*(__half2*)&u.w, *(__half2*)&v.w);
    float2 f0 = __half22float2(s0);
    float2 f1 = __half22float2(s1);
    float2 f2 = __half22float2(s2);
    float2 f3 = __half22float2(s3);
    a.x += f0.x; a.y += f0.y; a.z += f1.x; a.w += f1.y;
    b.x += f2.x; b.y += f2.y; b.z += f3.x; b.w += f3.y;
}

__device__ __forceinline__ void acc_one4(float4& a, float4& b, uint4 u) {
    float2 f0 = __half22float2(*(__half2*)&u.x);
    float2 f1 = __half22float2(*(__half2*)&u.y);
    float2 f2 = __half22float2(*(__half2*)&u.z);
    float2 f3 = __half22float2(*(__half2*)&u.w);
    a.x += f0.x; a.y += f0.y; a.z += f1.x; a.w += f1.y;
    b.x += f2.x; b.y += f2.y; b.z += f3.x; b.w += f3.y;
}

__global__ void __launch_bounds__(256) aggregate_k(const uint32_t* __restrict__ xin,
                                                   uint32_t* __restrict__ outp) {
    int warp = (blockIdx.x * blockDim.x + threadIdx.x) >> 5;
    int lane = threadIdx.x & 31;
    if (warp >= NN) return;
    int start = warp * CAP;               // computed, not loaded
    int end   = g_cursor[warp];
    const int hi  = lane >> 4;
    const int sub = lane & 15;
    const uint4* xv4 = (const uint4*)xin;

    float4 accA = make_float4(0.f, 0.f, 0.f, 0.f);
    float4 accB = make_float4(0.f, 0.f, 0.f, 0.f);
    int k = start;

    for (; k + 8 <= end; k += 8) {
        int i0 = g_csr[k + 0 + hi];
        int i1 = g_csr[k + 2 + hi];
        int i2 = g_csr[k + 4 + hi];
        int i3 = g_csr[k + 6 + hi];
        uint4 v0 = xv4[(size_t)i0 * 16 + sub];
        uint4 v1 = xv4[(size_t)i1 * 16 + sub];
        uint4 v2 = xv4[(size_t)i2 * 16 + sub];
        uint4 v3 = xv4[(size_t)i3 * 16 + sub];
        acc_pair4(accA, accB, v0, v1);
        acc_pair4(accA, accB, v2, v3);
    }
    if (k + 4 <= end) {
        int i0 = g_csr[k + 0 + hi];
        int i1 = g_csr[k + 2 + hi];
        uint4 v0 = xv4[(size_t)i0 * 16 + sub];
        uint4 v1 = xv4[(size_t)i1 * 16 + sub];
        acc_pair4(accA, accB, v0, v1);
        k += 4;
    }
    if (k + 2 <= end) {
        int i0 = g_csr[k + hi];
        uint4 v0 = xv4[(size_t)i0 * 16 + sub];
        acc_one4(accA, accB, v0);
        k += 2;
    }
    if (k < end && hi == 0) {
        uint4 v0 = xv4[(size_t)g_csr[k] * 16 + sub];
        acc_one4(accA, accB, v0);
    }

    float* pa = &accA.x;
    float* pb = &accB.x;
    #pragma unroll
    for (int i = 0; i < 4; i++) {
        pa[i] += __shfl_xor_sync(0xffffffffu, pa[i], 16);
        pb[i] += __shfl_xor_sync(0xffffffffu, pb[i], 16);
    }

    int deg = end - start;
    float inv = 1.0f / (float)(deg > 0 ? deg : 1);
    if (hi == 0) {
        uint4 o;
        o.x = pack_h2(accA.x * inv, accA.y * inv);
        o.y = pack_h2(accA.z * inv, accA.w * inv);
        o.z = pack_h2(accB.x * inv, accB.y * inv);
        o.w = pack_h2(accB.z * inv, accB.w * inv);
        ((uint4*)outp)[(size_t)warp * 16 + sub] = o;
    }
}

// ---------------- fp16 GEMM (m16n8k16, fp32 accum) with ldmatrix ------------
#define ROWW 20                       // words per smem row (16 data + 4 pad)
#define BUFW (128 * ROWW)             // words per buffer

__device__ __forceinline__ void cp_async16(uint32_t smem, const void* gptr, int src_sz) {
    asm volatile("cp.async.ca.shared.global [%0], [%1], 16, %2;"
                 :: "r"(smem), "l"(gptr), "r"(src_sz));
}
__device__ __forceinline__ void cp_commit() {
    asm volatile("cp.async.commit_group;");
}
template <int N>
__device__ __forceinline__ void cp_wait() {
    asm volatile("cp.async.wait_group %0;" :: "n"(N));
}

template <bool RELU>   // RELU version emits fp16 output only
__global__ void __launch_bounds__(256) gemm_f16_k(
    const uint32_t* __restrict__ A1,   // mean16 [NN][64]
    const uint32_t* __restrict__ A2,   // x16/h16 [NN][64]
    const uint32_t* __restrict__ Wl,   // [C][64] fp16
    const uint32_t* __restrict__ Wr,   // [C][64] fp16
    const float*    __restrict__ bias, // [C]
    float*          __restrict__ outp, // [NN][C] fp32 (final layer)
    uint32_t*       __restrict__ out16)// [NN][64] fp16 (hidden layer)
{
    __shared__ uint32_t As[2][BUFW];
    __shared__ uint32_t Ws[2][BUFW];

    const int tid  = threadIdx.x;
    const int lane = tid & 31;
    const int wid  = tid >> 5;
    const int warpRow = wid >> 2;
    const int warpCol = wid & 3;
    const int nodeBase = blockIdx.x * 128;

    const int lr = lane >> 2;
    const int lc = lane & 3;

    const uint32_t as_base = (uint32_t)__cvta_generic_to_shared(&As[0][0]);
    const uint32_t ws_base = (uint32_t)__cvta_generic_to_shared(&Ws[0][0]);

    // LDSM lane-address components (word offsets within a buffer)
    const int a_row = warpRow * 64 + (lane & 15);          // + mt*16
    const int a_colw = (lane >> 4) * 4;                    // + k0
    const int b_row = warpCol * 32 + (lane & 7) + ((lane >> 4) << 3);  // + p*16
    const int b_colw = ((lane >> 3) & 1) * 4;              // + k0

    float acc[4][4][4] = {};

    auto stage = [&](int s, int buf) {
        const int half = s >> 2;
        const int kw   = (s & 3) * 16;
        const uint32_t* A = half ? A2 : A1;
        const uint32_t* W = half ? Wr : Wl;
        #pragma unroll
        for (int t = 0; t < 2; t++) {
            int idx = tid + t * 256;
            int row = idx >> 2;
            int q   = idx & 3;
            int gnode = nodeBase + row;
            uint32_t off = (buf * BUFW + row * ROWW + q * 4) * 4;
            cp_async16(as_base + off, &A[(size_t)gnode * 64 + kw + q * 4],
                       (gnode < NN) ? 16 : 0);
            cp_async16(ws_base + off, &W[row * 64 + kw + q * 4], 16);
        }
        cp_commit();
    };

    stage(0, 0);

    #pragma unroll 1
    for (int s = 0; s < 8; s++) {
        const int buf = s & 1;
        if (s < 7) stage(s + 1, buf ^ 1);
        if (s < 7) cp_wait<1>(); else cp_wait<0>();
        __syncthreads();

        const uint32_t abuf = as_base + buf * BUFW * 4;
        const uint32_t wbuf = ws_base + buf * BUFW * 4;

        #pragma unroll
        for (int ks = 0; ks < 2; ks++) {
            const int k0 = ks * 8;
            uint32_t a[4][4];
            #pragma unroll
            for (int mt = 0; mt < 4; mt++) {
                uint32_t addr = abuf + ((a_row + mt * 16) * ROWW + k0 + a_colw) * 4;
                asm volatile(
                    "ldmatrix.sync.aligned.m8n8.x4.shared.b16 {%0,%1,%2,%3}, [%4];"
                    : "=r"(a[mt][0]), "=r"(a[mt][1]), "=r"(a[mt][2]), "=r"(a[mt][3])
                    : "r"(addr));
            }
            uint32_t bf[4][2];
            #pragma unroll
            for (int p = 0; p < 2; p++) {      // covers nt = 2p, 2p+1
                uint32_t addr = wbuf + ((b_row + p * 16) * ROWW + k0 + b_colw) * 4;
                asm volatile(
                    "ldmatrix.sync.aligned.m8n8.x4.shared.b16 {%0,%1,%2,%3}, [%4];"
                    : "=r"(bf[2 * p][0]), "=r"(bf[2 * p][1]),
                      "=r"(bf[2 * p + 1][0]), "=r"(bf[2 * p + 1][1])
                    : "r"(addr));
            }
            #pragma unroll
            for (int mt = 0; mt < 4; mt++) {
                #pragma unroll
                for (int nt = 0; nt < 4; nt++) {
                    asm volatile(
                        "mma.sync.aligned.m16n8k16.row.col.f32.f16.f16.f32 "
                        "{%0,%1,%2,%3}, {%4,%5,%6,%7}, {%8,%9}, {%0,%1,%2,%3};"
                        : "+f"(acc[mt][nt][0]), "+f"(acc[mt][nt][1]),
                          "+f"(acc[mt][nt][2]), "+f"(acc[mt][nt][3])
                        : "r"(a[mt][0]), "r"(a[mt][1]), "r"(a[mt][2]), "r"(a[mt][3]),
                          "r"(bf[nt][0]), "r"(bf[nt][1]));
                }
            }
        }
        __syncthreads();
    }

    #pragma unroll
    for (int nt = 0; nt < 4; nt++) {
        int c = warpCol * 32 + nt * 8 + 2 * lc;
        float bb0 = bias[c];
        float bb1 = bias[c + 1];
        #pragma unroll
        for (int mt = 0; mt < 4; mt++) {
            int r0 = nodeBase + warpRow * 64 + mt * 16 + lr;
            int r1 = r0 + 8;
            float o0 = acc[mt][nt][0] + bb0;
            float o1 = acc[mt][nt][1] + bb1;
            float o2 = acc[mt][nt][2] + bb0;
            float o3 = acc[mt][nt][3] + bb1;
            if (RELU) {
                o0 = fmaxf(o0, 0.f); o1 = fmaxf(o1, 0.f);
                o2 = fmaxf(o2, 0.f); o3 = fmaxf(o3, 0.f);
                if (r0 < NN) out16[(size_t)r0 * 64 + (c >> 1)] = pack_h2(o0, o1);
                if (r1 < NN) out16[(size_t)r1 * 64 + (c >> 1)] = pack_h2(o2, o3);
            } else {
                if (r0 < NN) *(float2*)&outp[(size_t)r0 * C + c] = make_float2(o0, o1);
                if (r1 < NN) *(float2*)&outp[(size_t)r1 * C + c] = make_float2(o2, o3);
            }
        }
    }
}

// ---------------- launch ----------------
extern "C" void kernel_launch(void* const* d_in, const int* in_sizes, int n_in,
                              void* d_out, int out_size) {
    const float* x   = (const float*)d_in[0];
    const void*  ei  = d_in[1];
    const float* W1l = (const float*)d_in[2];
    const float* b1  = (const float*)d_in[3];
    const float* W1r = (const float*)d_in[4];
    const float* W2l = (const float*)d_in[5];
    const float* b2  = (const float*)d_in[6];
    const float* W2r = (const float*)d_in[7];
    float* out = (float*)d_out;

    uint32_t *x16, *mean16, *h16, *w1l, *w1r, *w2l, *w2r;
    cudaGetSymbolAddress((void**)&x16,    g_x16);
    cudaGetSymbolAddress((void**)&mean16, g_mean16);
    cudaGetSymbolAddress((void**)&h16,    g_h16);
    cudaGetSymbolAddress((void**)&w1l,    g_W1l_h);
    cudaGetSymbolAddress((void**)&w1r,    g_W1r_h);
    cudaGetSymbolAddress((void**)&w2l,    g_W2l_h);
    cudaGetSymbolAddress((void**)&w2r,    g_W2r_h);

    const int gemmGrid = (NN + 127) / 128;  // 782

    init_cvt_k<<<(NN * 32 + 255) / 256, 256>>>((const float4*)x,
                                               W1l, W1r, W2l, W2r);              // 0
    csr_fill_k<<<(NE / 4 + 255) / 256, 256>>>(ei);                               // 1
    aggregate_k<<<(NN * 32 + 255) / 256, 256>>>(x16, mean16);                    // 2
    gemm_f16_k<true><<<gemmGrid, 256>>>(mean16, x16, w1l, w1r, b1, nullptr, h16); // 3 <- profiled
    aggregate_k<<<(NN * 32 + 255) / 256, 256>>>(h16, mean16);                    // 4
    gemm_f16_k<false><<<gemmGrid, 256>>>(mean16, h16, w2l, w2r, b2, out, nullptr); // 5
}